// round 1
// baseline (speedup 1.0000x reference)
#include <cuda_runtime.h>

#define NN   8192
#define FIN  128
#define FOUT 64
#define ALPHA 0.2f
#define LOG2E 1.4426950408889634f

#define TI 64
#define TJ 32
#define WS_STRIDE 33   // padded float2 row stride (banks conflict-free for consumer)

// ---- device scratch (no allocations allowed) ----
__device__ float g_h[NN * FOUT];   // 2 MB
__device__ float g_s1[NN];
__device__ float g_s2[NN];

__device__ __forceinline__ float ex2f(float x) {
    float r; asm("ex2.approx.ftz.f32 %0, %1;" : "=f"(r) : "f"(x)); return r;
}
__device__ __forceinline__ unsigned long long dup2(float w) {
    unsigned long long r; unsigned int u = __float_as_uint(w);
    asm("mov.b64 %0, {%1, %2};" : "=l"(r) : "r"(u), "r"(u)); return r;
}
__device__ __forceinline__ void unpk(unsigned long long v, float &lo, float &hi) {
    unsigned int a, b;
    asm("mov.b64 {%0, %1}, %2;" : "=r"(a), "=r"(b) : "l"(v));
    lo = __uint_as_float(a); hi = __uint_as_float(b);
}
#define FMA2(d, a, b) asm("fma.rn.f32x2 %0, %1, %2, %0;" : "+l"(d) : "l"(a), "l"(b))

// ===================== K1: h = X@W ; s1,s2 (pre-scaled by log2 e) =====================
__global__ __launch_bounds__(256) void k_proj(const float* __restrict__ X,
                                              const float* __restrict__ W,
                                              const float* __restrict__ a1,
                                              const float* __restrict__ a2) {
    __shared__ float Xs[4 * FIN];
    __shared__ float Ws[FIN * FOUT];
    __shared__ float part1[4][2], part2[4][2];
    const int tid = threadIdx.x;
    const int i0 = blockIdx.x * 4;

    const float4* W4 = (const float4*)W;
    float4* Ws4 = (float4*)Ws;
#pragma unroll
    for (int k = 0; k < 8; k++) Ws4[tid + k * 256] = W4[tid + k * 256];
    if (tid < 128) ((float4*)Xs)[tid] = ((const float4*)(X + (size_t)i0 * FIN))[tid];
    __syncthreads();

    const int il = tid >> 6, f = tid & 63;
    float acc = 0.f;
#pragma unroll
    for (int k = 0; k < FIN; k++) acc += Xs[il * FIN + k] * Ws[k * FOUT + f];
    g_h[(size_t)(i0 + il) * FOUT + f] = acc;

    float v1 = acc * a1[f];
    float v2 = acc * a2[f];
#pragma unroll
    for (int s = 16; s > 0; s >>= 1) {
        v1 += __shfl_xor_sync(0xffffffffu, v1, s);
        v2 += __shfl_xor_sync(0xffffffffu, v2, s);
    }
    const int half = (tid >> 5) & 1;
    if ((tid & 31) == 0) { part1[il][half] = v1; part2[il][half] = v2; }
    __syncthreads();
    if (f == 0) {
        g_s1[i0 + il] = (part1[il][0] + part1[il][1]) * LOG2E;
        g_s2[i0 + il] = (part2[il][0] + part2[il][1]) * LOG2E;
    }
}

// ===================== K2: fused masked softmax + aggregation =====================
// out[i] = sum_j A_ij * exp2(max(t,0.2t)) * h[j] / wsum,  t = s1'[i]+s2'[j]
__global__ __launch_bounds__(256) void k_gat(const int* __restrict__ A,
                                             float* __restrict__ out) {
    __shared__ float hs[TJ * FOUT];                       // 8 KB
    __shared__ unsigned long long ws2[TI * WS_STRIDE];    // 16.9 KB, (w,w) pairs
    __shared__ float s1s[TI];
    __shared__ float wsum_s[TI];

    const int tid = threadIdx.x;
    const int i0 = blockIdx.x * TI;

    if (tid < TI) s1s[tid] = g_s1[i0 + tid];

    // producer mapping: 8 lanes (jj4) x 32 rows (iw), 2 passes over ii
    const int jj4 = tid & 7;
    const int iw  = tid >> 3;
    // consumer mapping: 16 f-groups x 16 i-groups, 4x4 register tile
    const int fgrp = tid & 15;
    const int igrp = tid >> 4;
    const int f0 = fgrp * 4;
    const int ii0 = igrp * 4;

    unsigned long long acc[8];
#pragma unroll
    for (int k = 0; k < 8; k++) acc[k] = 0ull;
    float wsA0 = 0.f, wsA1 = 0.f;

    const int4* Arow0 = (const int4*)(A + (size_t)(i0 + iw) * NN);
    const int4* Arow1 = (const int4*)(A + (size_t)(i0 + 32 + iw) * NN);

    // prefetch tile 0
    int4 a_c0 = Arow0[jj4];
    int4 a_c1 = Arow1[jj4];
    float4 s2_c = *(const float4*)(g_s2 + jj4 * 4);
    const float4* hsrc = (const float4*)g_h;
    float4 h_c0 = hsrc[tid];
    float4 h_c1 = hsrc[tid + 256];

    __syncthreads();  // s1s ready; smem free

    const int NTILES = NN / TJ;
    for (int t = 0; t < NTILES; t++) {
        // stage h tile into smem
        ((float4*)hs)[tid] = h_c0;
        ((float4*)hs)[tid + 256] = h_c1;

        // w-phase from prefetched registers
#pragma unroll
        for (int p = 0; p < 2; p++) {
            const int ii = p * 32 + iw;
            const int4 a = p ? a_c1 : a_c0;
            const float t0 = s1s[ii];
            float x, w0, w1, w2, w3;
            x = t0 + s2_c.x; w0 = (a.x > 0) ? ex2f(fmaxf(x, ALPHA * x)) : 0.f;
            x = t0 + s2_c.y; w1 = (a.y > 0) ? ex2f(fmaxf(x, ALPHA * x)) : 0.f;
            x = t0 + s2_c.z; w2 = (a.z > 0) ? ex2f(fmaxf(x, ALPHA * x)) : 0.f;
            x = t0 + s2_c.w; w3 = (a.w > 0) ? ex2f(fmaxf(x, ALPHA * x)) : 0.f;
            unsigned long long* wrow = &ws2[ii * WS_STRIDE + jj4 * 4];
            wrow[0] = dup2(w0); wrow[1] = dup2(w1);
            wrow[2] = dup2(w2); wrow[3] = dup2(w3);
            float s = (w0 + w1) + (w2 + w3);
            s += __shfl_xor_sync(0xffffffffu, s, 1);
            s += __shfl_xor_sync(0xffffffffu, s, 2);
            s += __shfl_xor_sync(0xffffffffu, s, 4);
            if (p == 0) wsA0 += s; else wsA1 += s;
        }

        // prefetch tile t+1 (hides DRAM/L2 latency behind the rank-update)
        if (t + 1 < NTILES) {
            const int jn = (t + 1) * TJ;
            a_c0 = Arow0[jn / 4 + jj4];
            a_c1 = Arow1[jn / 4 + jj4];
            s2_c = *(const float4*)(g_s2 + jn + jj4 * 4);
            const float4* hn = (const float4*)(g_h + (size_t)jn * FOUT);
            h_c0 = hn[tid];
            h_c1 = hn[tid + 256];
        }
        __syncthreads();  // hs + ws2 visible

        // rank-TJ update: acc[4i][4f] += w * h  (packed f32x2)
#pragma unroll 8
        for (int jj = 0; jj < TJ; jj++) {
            const ulonglong2 hv = *(const ulonglong2*)(hs + jj * FOUT + f0);
#pragma unroll
            for (int k = 0; k < 4; k++) {
                const unsigned long long wp = ws2[(ii0 + k) * WS_STRIDE + jj];
                FMA2(acc[2 * k],     wp, hv.x);
                FMA2(acc[2 * k + 1], wp, hv.y);
            }
        }
        __syncthreads();  // before next tile overwrites hs/ws2
    }

    // publish row sums (same thread owned each ii every tile -> no race)
    if (jj4 == 0) { wsum_s[iw] = wsA0; wsum_s[32 + iw] = wsA1; }
    __syncthreads();

#pragma unroll
    for (int k = 0; k < 4; k++) {
        const float inv = 1.0f / wsum_s[ii0 + k];
        float x0, x1, x2, x3;
        unpk(acc[2 * k], x0, x1);
        unpk(acc[2 * k + 1], x2, x3);
        float4 o = make_float4(x0 * inv, x1 * inv, x2 * inv, x3 * inv);
        *(float4*)(out + (size_t)(i0 + ii0 + k) * FOUT + f0) = o;
    }
}

extern "C" void kernel_launch(void* const* d_in, const int* in_sizes, int n_in,
                              void* d_out, int out_size) {
    const float* X  = (const float*)d_in[0];
    const int*   A  = (const int*)d_in[1];
    const float* W  = (const float*)d_in[2];
    const float* a1 = (const float*)d_in[3];
    const float* a2 = (const float*)d_in[4];
    float* out = (float*)d_out;

    k_proj<<<NN / 4, 256>>>(X, W, a1, a2);
    k_gat<<<NN / TI, 256>>>(A, out);
}

// round 3
// speedup vs baseline: 3.2485x; 3.2485x over previous
#include <cuda_runtime.h>
#include <cstdint>

#define NN    8192
#define FIN   128
#define FOUT  64
#define ALPHA 0.2f
#define LOG2E 1.4426950408889634f

#define TI  128        // i rows per CTA
#define JH  4096       // j range per CTA (2-way split-K)
#define KC  64         // j chunk
#define NCH (JH/KC)    // 64 chunks

// smem layout (dynamic): padded stride 68 (mod 32 == 4 -> bank = 4*qr+qc, bijective)
#define AS_BYTES   (128*68*4)          // 34816 per buffer
#define HS_BYTES   (64*68*4)           // 17408 per buffer
#define EF_BYTES   (64*8)              // 512 per buffer
#define SMEM_SZ    (2*AS_BYTES + 2*HS_BYTES + 2*EF_BYTES)   // 105472

// ---------------- device scratch ----------------
__device__ float  g_hT[(size_t)FOUT * NN];   // h^T, tf32-rounded f32, [f][j]
__device__ float2 g_EF1[NN];                 // {exp2(s1'), exp2(0.2*s1')}
__device__ float2 g_EF2[NN];                 // {exp2(s2'), exp2(0.2*s2')}
__device__ float  g_part[2][(size_t)NN * FOUT];
__device__ float  g_wsum[2][NN];

// ---------------- helpers ----------------
__device__ __forceinline__ float ex2f(float x) {
    float r; asm("ex2.approx.ftz.f32 %0, %1;" : "=f"(r) : "f"(x)); return r;
}
__device__ __forceinline__ uint32_t smem_u32(const void* p) {
    uint32_t a;
    asm("{ .reg .u64 t; cvta.to.shared.u64 t, %1; cvt.u32.u64 %0, t; }" : "=r"(a) : "l"(p));
    return a;
}
__device__ __forceinline__ float tf32r(float x) {
    uint32_t u; asm("cvt.rna.tf32.f32 %0, %1;" : "=r"(u) : "f"(x));
    return __uint_as_float(u);
}

#define CP16(dst, src) \
    asm volatile("cp.async.cg.shared.global [%0], [%1], 16;" :: "r"(dst), "l"(src) : "memory")
#define CP_COMMIT() asm volatile("cp.async.commit_group;" ::: "memory")
#define CP_WAIT1()  asm volatile("cp.async.wait_group 1;" ::: "memory")
#define CP_WAIT0()  asm volatile("cp.async.wait_group 0;" ::: "memory")

__device__ __forceinline__ int lds_s32(uint32_t a) {
    int v; asm volatile("ld.shared.b32 %0, [%1];" : "=r"(v) : "r"(a)); return v;
}
__device__ __forceinline__ uint32_t lds_u32(uint32_t a) {
    uint32_t v; asm volatile("ld.shared.b32 %0, [%1];" : "=r"(v) : "r"(a)); return v;
}
__device__ __forceinline__ float2 lds_f2(uint32_t a) {
    float2 v; asm volatile("ld.shared.v2.f32 {%0,%1}, [%2];" : "=f"(v.x), "=f"(v.y) : "r"(a)); return v;
}

#define MMA_TF32(c, a0, a1, a2, a3, b0, b1) \
    asm volatile("mma.sync.aligned.m16n8k8.row.col.f32.tf32.tf32.f32 " \
        "{%0,%1,%2,%3}, {%4,%5,%6,%7}, {%8,%9}, {%0,%1,%2,%3};" \
        : "+f"((c)[0]), "+f"((c)[1]), "+f"((c)[2]), "+f"((c)[3]) \
        : "r"(a0), "r"(a1), "r"(a2), "r"(a3), "r"(b0), "r"(b1))

// ===================== K1: projection + node tables =====================
__global__ __launch_bounds__(256) void k_proj(const float* __restrict__ X,
                                              const float* __restrict__ W,
                                              const float* __restrict__ a1,
                                              const float* __restrict__ a2) {
    __shared__ float Xs[4 * FIN];
    __shared__ float Ws[FIN * FOUT];
    __shared__ float part1[4][2], part2[4][2];
    const int tid = threadIdx.x;
    const int i0 = blockIdx.x * 4;

    const float4* W4 = (const float4*)W;
    float4* Ws4 = (float4*)Ws;
#pragma unroll
    for (int k = 0; k < 8; k++) Ws4[tid + k * 256] = W4[tid + k * 256];
    if (tid < 128) ((float4*)Xs)[tid] = ((const float4*)(X + (size_t)i0 * FIN))[tid];
    __syncthreads();

    const int il = tid >> 6, f = tid & 63;
    float acc = 0.f;
#pragma unroll
    for (int k = 0; k < FIN; k++) acc += Xs[il * FIN + k] * Ws[k * FOUT + f];

    // h^T (tf32-rounded) for the MMA B operand
    g_hT[(size_t)f * NN + i0 + il] = tf32r(acc);

    float v1 = acc * a1[f];
    float v2 = acc * a2[f];
#pragma unroll
    for (int s = 16; s > 0; s >>= 1) {
        v1 += __shfl_xor_sync(0xffffffffu, v1, s);
        v2 += __shfl_xor_sync(0xffffffffu, v2, s);
    }
    const int half = (tid >> 5) & 1;
    if ((tid & 31) == 0) { part1[il][half] = v1; part2[il][half] = v2; }
    __syncthreads();

    if (f == 0) {
        const float s1L = (part1[il][0] + part1[il][1]) * LOG2E;
        const float s2L = (part2[il][0] + part2[il][1]) * LOG2E;
        const int node = i0 + il;
        g_EF1[node] = make_float2(ex2f(s1L), ex2f(ALPHA * s1L));
        g_EF2[node] = make_float2(ex2f(s2L), ex2f(ALPHA * s2L));
    }
}

// ===================== K2: fused masked softmax + aggregation (TF32 MMA) =====================
__global__ __launch_bounds__(256, 1) void k_gat(const int* __restrict__ A) {
    extern __shared__ char sm[];
    const uint32_t sb = smem_u32(sm);

    const int tid  = threadIdx.x;
    const int wid  = tid >> 5;
    const int lane = tid & 31;
    const int qr   = lane >> 2;     // 0..7
    const int qc   = lane & 3;      // 0..3
    const int ib   = blockIdx.x >> 1;
    const int half = blockIdx.x & 1;
    const int i0   = ib * TI;
    const int j0   = half * JH;

    const uint32_t asB[2] = { sb,                sb + AS_BYTES };
    const uint32_t hsB[2] = { sb + 2*AS_BYTES,   sb + 2*AS_BYTES + HS_BYTES };
    const uint32_t efB[2] = { sb + 2*AS_BYTES + 2*HS_BYTES,
                              sb + 2*AS_BYTES + 2*HS_BYTES + EF_BYTES };

    // per-thread cp.async bases
    const int prow = tid >> 4;          // 0..15
    const int pcol = (tid & 15) * 4;    // int/float offset within chunk row
    const int*   aSrc = A    + (size_t)(i0 + prow) * NN + j0 + pcol;
    const float* hSrc = g_hT + (size_t)prow * NN        + j0 + pcol;
    const uint32_t aDstOff = (uint32_t)(prow * 68 + pcol) * 4;
    const uint32_t hDstOff = aDstOff;

    // row tables
    const int r0g = i0 + wid * 16 + qr;
    const float2 ef1a = g_EF1[r0g];
    const float2 ef1b = g_EF1[r0g + 8];

    float acc[8][4];
#pragma unroll
    for (int n = 0; n < 8; n++)
#pragma unroll
        for (int k = 0; k < 4; k++) acc[n][k] = 0.f;
    float wsum0 = 0.f, wsum1 = 0.f;

#define ISSUE(T, P) do {                                                         \
        const int _jo = (T) * KC;                                                \
        _Pragma("unroll")                                                        \
        for (int k = 0; k < 8; k++)                                              \
            CP16(asB[P] + aDstOff + (uint32_t)(k * 16 * 68 * 4),                 \
                 aSrc + (size_t)k * 16 * NN + _jo);                              \
        _Pragma("unroll")                                                        \
        for (int k = 0; k < 4; k++)                                              \
            CP16(hsB[P] + hDstOff + (uint32_t)(k * 16 * 68 * 4),                 \
                 hSrc + (size_t)k * 16 * NN + _jo);                              \
        if (tid < 32)                                                            \
            CP16(efB[P] + (uint32_t)tid * 16, (const float2*)g_EF2 + j0 + _jo + tid * 2); \
        CP_COMMIT();                                                             \
    } while (0)

    ISSUE(0, 0);

    for (int t = 0; t < NCH; t++) {
        const int p = t & 1;
        if (t + 1 < NCH) { ISSUE(t + 1, p ^ 1); CP_WAIT1(); }
        else             { CP_WAIT0(); }
        __syncthreads();

        const uint32_t asb = asB[p] + (uint32_t)((wid * 16 + qr) * 68 + qc) * 4;
        const uint32_t hsb = hsB[p] + (uint32_t)(qr * 68 + qc) * 4;
        const uint32_t efb = efB[p] + (uint32_t)qc * 8;

#pragma unroll
        for (int ks = 0; ks < 8; ks++) {
            const uint32_t jw = (uint32_t)(ks * 8) * 4;   // byte offset of jl within row
            // A mask bits for this thread's 4 fragment slots
            const int a00 = lds_s32(asb + jw);
            const int a01 = lds_s32(asb + jw + 16);
            const int a10 = lds_s32(asb + jw + 8 * 68 * 4);
            const int a11 = lds_s32(asb + jw + 8 * 68 * 4 + 16);
            const float2 ef0 = lds_f2(efb + (uint32_t)(ks * 8) * 8);
            const float2 ef4 = lds_f2(efb + (uint32_t)(ks * 8) * 8 + 32);

            float w00 = fmaxf(ef1a.x * ef0.x, ef1a.y * ef0.y); if (a00 <= 0) w00 = 0.f;
            float w01 = fmaxf(ef1a.x * ef4.x, ef1a.y * ef4.y); if (a01 <= 0) w01 = 0.f;
            float w10 = fmaxf(ef1b.x * ef0.x, ef1b.y * ef0.y); if (a10 <= 0) w10 = 0.f;
            float w11 = fmaxf(ef1b.x * ef4.x, ef1b.y * ef4.y); if (a11 <= 0) w11 = 0.f;
            wsum0 += w00 + w01;
            wsum1 += w10 + w11;

            const uint32_t ua0 = __float_as_uint(w00);  // (r, c)
            const uint32_t ua1 = __float_as_uint(w10);  // (r+8, c)
            const uint32_t ua2 = __float_as_uint(w01);  // (r, c+4)
            const uint32_t ua3 = __float_as_uint(w11);  // (r+8, c+4)

#pragma unroll
            for (int nt = 0; nt < 8; nt++) {
                const uint32_t hb = hsb + (uint32_t)(nt * 8 * 68 * 4) + jw;
                const uint32_t b0 = lds_u32(hb);        // B[k=qc][n=nt*8+qr]
                const uint32_t b1 = lds_u32(hb + 16);   // B[k=qc+4][n]
                MMA_TF32(acc[nt], ua0, ua1, ua2, ua3, b0, b1);
            }
        }
        __syncthreads();
    }

    // ---- epilogue: reduce wsum over qc lanes, store partials ----
    wsum0 += __shfl_xor_sync(0xffffffffu, wsum0, 1);
    wsum0 += __shfl_xor_sync(0xffffffffu, wsum0, 2);
    wsum1 += __shfl_xor_sync(0xffffffffu, wsum1, 1);
    wsum1 += __shfl_xor_sync(0xffffffffu, wsum1, 2);
    if (qc == 0) {
        g_wsum[half][r0g]     = wsum0;
        g_wsum[half][r0g + 8] = wsum1;
    }

    float* p0 = &g_part[half][(size_t)r0g * FOUT];
    float* p1 = &g_part[half][(size_t)(r0g + 8) * FOUT];
#pragma unroll
    for (int nt = 0; nt < 8; nt++) {
        const int c0 = nt * 8 + 2 * qc;
        *(float2*)(p0 + c0) = make_float2(acc[nt][0], acc[nt][1]);
        *(float2*)(p1 + c0) = make_float2(acc[nt][2], acc[nt][3]);
    }
}

// ===================== K3: combine halves + divide =====================
__global__ __launch_bounds__(512) void k_div(float* __restrict__ out) {
    const int idx = blockIdx.x * 512 + threadIdx.x;
    const int i = idx >> 6;
    const float num = g_part[0][idx] + g_part[1][idx];
    const float den = g_wsum[0][i] + g_wsum[1][i];
    out[idx] = num / den;
}

extern "C" void kernel_launch(void* const* d_in, const int* in_sizes, int n_in,
                              void* d_out, int out_size) {
    const float* X  = (const float*)d_in[0];
    const int*   A  = (const int*)d_in[1];
    const float* W  = (const float*)d_in[2];
    const float* a1 = (const float*)d_in[3];
    const float* a2 = (const float*)d_in[4];
    float* out = (float*)d_out;

    static bool attr_done = false;
    if (!attr_done) {
        cudaFuncSetAttribute(k_gat, cudaFuncAttributeMaxDynamicSharedMemorySize, SMEM_SZ);
        attr_done = true;
    }

    k_proj<<<NN / 4, 256>>>(X, W, a1, a2);
    k_gat<<<2 * (NN / TI), 256, SMEM_SZ>>>(A);
    k_div<<<NN * FOUT / 512, 512>>>(out);
}

// round 4
// speedup vs baseline: 3.7560x; 1.1562x over previous
#include <cuda_runtime.h>
#include <cstdint>

#define NN    8192
#define FIN   128
#define FOUT  64
#define ALPHA 0.2f
#define LOG2E 1.4426950408889634f

#define TI    128        // i rows per CTA
#define SPLIT 4          // split-K ways
#define JH    (NN/SPLIT) // 2048 j per CTA
#define KC    32         // j chunk
#define NCH   (JH/KC)    // 64 chunks

// k_gat smem layout (stride 36 floats: bank = (4*row + col) mod 32, conflict-free)
#define A_BUF  (128*36*4)        // 18432
#define H_BUF  (64*36*4)         // 9216
#define EF_BUF 256
#define OFF_A(p)   ((uint32_t)((p)*A_BUF))
#define OFF_H(p)   ((uint32_t)(2*A_BUF + (p)*H_BUF))
#define OFF_EF(p)  ((uint32_t)(2*A_BUF + 2*H_BUF + (p)*EF_BUF))
#define GAT_SMEM   (2*A_BUF + 2*H_BUF + 2*EF_BUF + 128)   // 55936

#define PROJ_SMEM  ((8192 + 128*36) * 4)                  // 51200

// ---------------- device scratch ----------------
__device__ float  g_hT[(size_t)FOUT * NN];   // h^T (tf32-rounded), [f][j]
__device__ float2 g_EF1[NN];                 // {exp2(s1'), exp2(0.2 s1')}
__device__ float2 g_EF2[NN];
__device__ float  g_part[SPLIT][(size_t)NN * FOUT];
__device__ float  g_wsum[SPLIT][NN];

// ---------------- helpers ----------------
__device__ __forceinline__ float ex2f(float x) {
    float r; asm("ex2.approx.ftz.f32 %0, %1;" : "=f"(r) : "f"(x)); return r;
}
__device__ __forceinline__ uint32_t smem_u32(const void* p) {
    uint32_t a;
    asm("{ .reg .u64 t; cvta.to.shared.u64 t, %1; cvt.u32.u64 %0, t; }" : "=r"(a) : "l"(p));
    return a;
}
__device__ __forceinline__ float tf32r(float x) {
    uint32_t u; asm("cvt.rna.tf32.f32 %0, %1;" : "=r"(u) : "f"(x));
    return __uint_as_float(u);
}

#define CP16(dst, src) \
    asm volatile("cp.async.cg.shared.global [%0], [%1], 16;" :: "r"(dst), "l"(src) : "memory")
#define CP_COMMIT() asm volatile("cp.async.commit_group;" ::: "memory")
#define CP_WAIT1()  asm volatile("cp.async.wait_group 1;" ::: "memory")
#define CP_WAIT0()  asm volatile("cp.async.wait_group 0;" ::: "memory")

__device__ __forceinline__ int lds_s32(uint32_t a) {
    int v; asm volatile("ld.shared.b32 %0, [%1];" : "=r"(v) : "r"(a)); return v;
}
__device__ __forceinline__ uint32_t lds_u32(uint32_t a) {
    uint32_t v; asm volatile("ld.shared.b32 %0, [%1];" : "=r"(v) : "r"(a)); return v;
}
__device__ __forceinline__ float2 lds_f2(uint32_t a) {
    float2 v; asm volatile("ld.shared.v2.f32 {%0,%1}, [%2];" : "=f"(v.x), "=f"(v.y) : "r"(a)); return v;
}

#define MMA_TF32(c, a0, a1, a2, a3, b0, b1) \
    asm volatile("mma.sync.aligned.m16n8k8.row.col.f32.tf32.tf32.f32 " \
        "{%0,%1,%2,%3}, {%4,%5,%6,%7}, {%8,%9}, {%0,%1,%2,%3};" \
        : "+f"((c)[0]), "+f"((c)[1]), "+f"((c)[2]), "+f"((c)[3]) \
        : "r"(a0), "r"(a1), "r"(a2), "r"(a3), "r"(b0), "r"(b1))

// ===================== K1: projection + node tables =====================
// 256 CTAs x 32 rows; thread tile 4 rows x 2 cols.
__global__ __launch_bounds__(256) void k_proj(const float* __restrict__ X,
                                              const float* __restrict__ W,
                                              const float* __restrict__ a1,
                                              const float* __restrict__ a2) {
    extern __shared__ float psm[];
    float* Ws = psm;            // [k][f] 128x64
    float* Xs = psm + 8192;     // [k][row] 128 x stride 36

    const int tid = threadIdx.x;
    const int i0 = blockIdx.x * 32;

    // W: straight copy (row-major [k][f])
    {
        const float4* W4 = (const float4*)W;
        float4* Ws4 = (float4*)Ws;
#pragma unroll
        for (int k = 0; k < 8; k++) Ws4[tid + k * 256] = W4[tid + k * 256];
    }
    // X: transpose into Xs[k][row]
    {
        const int row = tid & 31;
        const int sg0 = tid >> 5;
#pragma unroll
        for (int it = 0; it < 4; it++) {
            const int seg = sg0 + it * 8;
            const float4 v = *(const float4*)(X + (size_t)(i0 + row) * FIN + seg * 4);
            Xs[(4 * seg + 0) * 36 + row] = v.x;
            Xs[(4 * seg + 1) * 36 + row] = v.y;
            Xs[(4 * seg + 2) * 36 + row] = v.z;
            Xs[(4 * seg + 3) * 36 + row] = v.w;
        }
    }
    __syncthreads();

    const int cg = tid & 31;     // col pair
    const int rg = tid >> 5;     // row group (4 rows)
    const float2 a1v = ((const float2*)a1)[cg];
    const float2 a2v = ((const float2*)a2)[cg];

    float acc[4][2];
#pragma unroll
    for (int r = 0; r < 4; r++) { acc[r][0] = 0.f; acc[r][1] = 0.f; }

#pragma unroll 8
    for (int k = 0; k < FIN; k++) {
        const float2 wv = *(const float2*)(Ws + k * 64 + 2 * cg);
        const float4 xv = *(const float4*)(Xs + k * 36 + rg * 4);
        acc[0][0] += xv.x * wv.x; acc[0][1] += xv.x * wv.y;
        acc[1][0] += xv.y * wv.x; acc[1][1] += xv.y * wv.y;
        acc[2][0] += xv.z * wv.x; acc[2][1] += xv.z * wv.y;
        acc[3][0] += xv.w * wv.x; acc[3][1] += xv.w * wv.y;
    }

    // h^T (tf32-rounded)
    {
        const float4 c0 = make_float4(tf32r(acc[0][0]), tf32r(acc[1][0]), tf32r(acc[2][0]), tf32r(acc[3][0]));
        const float4 c1 = make_float4(tf32r(acc[0][1]), tf32r(acc[1][1]), tf32r(acc[2][1]), tf32r(acc[3][1]));
        *(float4*)(g_hT + (size_t)(2 * cg) * NN + i0 + rg * 4) = c0;
        *(float4*)(g_hT + (size_t)(2 * cg + 1) * NN + i0 + rg * 4) = c1;
    }

    // s1, s2 partials over this thread's 2 cols, reduce across warp (32 col-pairs)
    float v1[4], v2[4];
#pragma unroll
    for (int r = 0; r < 4; r++) {
        v1[r] = acc[r][0] * a1v.x + acc[r][1] * a1v.y;
        v2[r] = acc[r][0] * a2v.x + acc[r][1] * a2v.y;
    }
#pragma unroll
    for (int s = 16; s > 0; s >>= 1) {
#pragma unroll
        for (int r = 0; r < 4; r++) {
            v1[r] += __shfl_xor_sync(0xffffffffu, v1[r], s);
            v2[r] += __shfl_xor_sync(0xffffffffu, v2[r], s);
        }
    }
    if (cg < 4) {
        const float s1L = v1[cg] * LOG2E;
        const float s2L = v2[cg] * LOG2E;
        const int node = i0 + rg * 4 + cg;
        g_EF1[node] = make_float2(ex2f(s1L), ex2f(ALPHA * s1L));
        g_EF2[node] = make_float2(ex2f(s2L), ex2f(ALPHA * s2L));
    }
}

// ===================== K2: fused masked softmax + aggregation (TF32 MMA) =====================
// grid = 64*SPLIT = 256 CTAs, 2 CTAs/SM. Warp tile m32 x n32 (8 warps = 4 m-groups x 2 n-groups).
__global__ __launch_bounds__(256, 2) void k_gat(const int* __restrict__ A) {
    extern __shared__ char sm[];
    const uint32_t sb0 = smem_u32(sm);
    const uint32_t sb = (sb0 + 127u) & ~127u;

    const int tid  = threadIdx.x;
    const int wid  = tid >> 5;
    const int lane = tid & 31;
    const int qr   = lane >> 2;     // 0..7
    const int qc   = lane & 3;      // 0..3
    const int mg   = wid >> 1;      // 0..3  (m-group: rows mg*32..+31)
    const int ng   = wid & 1;       // 0..1  (n-group: cols ng*32..+31)
    const int ib   = blockIdx.x >> 2;
    const int sk   = blockIdx.x & 3;
    const int i0   = ib * TI;
    const int j0   = sk * JH;

    // cp.async source/dest mapping
    const int prow = tid >> 3;          // 0..31
    const int pseg = (tid & 7) * 4;     // 16B segment (4 ints/floats)
    const int*   aSrc = A    + (size_t)(i0 + prow) * NN + j0 + pseg;
    const float* hSrc = g_hT + (size_t)prow * NN        + j0 + pseg;
    const uint32_t aOff = (uint32_t)(prow * 36 + pseg) * 4;

    // per-thread row tables: rows mg*32 + {qr, qr+8, qr+16, qr+24}
    float2 ef1[4];
#pragma unroll
    for (int k = 0; k < 4; k++) ef1[k] = g_EF1[i0 + mg * 32 + qr + 8 * k];

    float acc[2][4][4];
#pragma unroll
    for (int mt = 0; mt < 2; mt++)
#pragma unroll
        for (int nt = 0; nt < 4; nt++)
#pragma unroll
            for (int k = 0; k < 4; k++) acc[mt][nt][k] = 0.f;
    float wsum[4] = {0.f, 0.f, 0.f, 0.f};

#define ISSUE(T, P) do {                                                           \
        const int _jo = (T) * KC;                                                  \
        _Pragma("unroll")                                                          \
        for (int k = 0; k < 4; k++)                                                \
            CP16(sb + OFF_A(P) + aOff + (uint32_t)(k * 32 * 36 * 4),               \
                 aSrc + (size_t)k * 32 * NN + _jo);                                \
        _Pragma("unroll")                                                          \
        for (int k = 0; k < 2; k++)                                                \
            CP16(sb + OFF_H(P) + aOff + (uint32_t)(k * 32 * 36 * 4),               \
                 hSrc + (size_t)k * 32 * NN + _jo);                                \
        if (tid < 16)                                                              \
            CP16(sb + OFF_EF(P) + (uint32_t)tid * 16,                              \
                 (const float2*)g_EF2 + j0 + _jo + tid * 2);                       \
        CP_COMMIT();                                                               \
    } while (0)

    ISSUE(0, 0);

    for (int t = 0; t < NCH; t++) {
        const int p = t & 1;
        if (t + 1 < NCH) { ISSUE(t + 1, p ^ 1); CP_WAIT1(); }
        else             { CP_WAIT0(); }
        __syncthreads();

        const uint32_t asb = sb + OFF_A(p) + (uint32_t)((mg * 32 + qr) * 36 + qc) * 4;
        const uint32_t hsb = sb + OFF_H(p) + (uint32_t)((ng * 32 + qr) * 36 + qc) * 4;
        const uint32_t efb = sb + OFF_EF(p) + (uint32_t)qc * 8;

#pragma unroll
        for (int ks = 0; ks < 4; ks++) {
            const uint32_t jw = (uint32_t)ks * 32;     // byte offset of j within row

            const float2 ef0 = lds_f2(efb + (uint32_t)ks * 64);
            const float2 ef4 = lds_f2(efb + (uint32_t)ks * 64 + 32);

            // B fragments for all 4 n-tiles (shared across both m-tiles)
            uint32_t b[4][2];
#pragma unroll
            for (int nt = 0; nt < 4; nt++) {
                const uint32_t hb = hsb + (uint32_t)(nt * 8 * 36 * 4) + jw;
                b[nt][0] = lds_u32(hb);
                b[nt][1] = lds_u32(hb + 16);
            }

#pragma unroll
            for (int mt = 0; mt < 2; mt++) {
                const uint32_t ab = asb + (uint32_t)(mt * 16 * 36 * 4) + jw;
                const int a00 = lds_s32(ab);
                const int a01 = lds_s32(ab + 16);
                const int a10 = lds_s32(ab + 8 * 36 * 4);
                const int a11 = lds_s32(ab + 8 * 36 * 4 + 16);

                const float2 e1a = ef1[2 * mt];
                const float2 e1b = ef1[2 * mt + 1];
                float w00 = fmaxf(e1a.x * ef0.x, e1a.y * ef0.y); if (a00 <= 0) w00 = 0.f;
                float w01 = fmaxf(e1a.x * ef4.x, e1a.y * ef4.y); if (a01 <= 0) w01 = 0.f;
                float w10 = fmaxf(e1b.x * ef0.x, e1b.y * ef0.y); if (a10 <= 0) w10 = 0.f;
                float w11 = fmaxf(e1b.x * ef4.x, e1b.y * ef4.y); if (a11 <= 0) w11 = 0.f;
                wsum[2 * mt]     += w00 + w01;
                wsum[2 * mt + 1] += w10 + w11;

                const uint32_t ua0 = __float_as_uint(w00);
                const uint32_t ua1 = __float_as_uint(w10);
                const uint32_t ua2 = __float_as_uint(w01);
                const uint32_t ua3 = __float_as_uint(w11);

#pragma unroll
                for (int nt = 0; nt < 4; nt++)
                    MMA_TF32(acc[mt][nt], ua0, ua1, ua2, ua3, b[nt][0], b[nt][1]);
            }
        }
        __syncthreads();
    }

    // ---- epilogue ----
    // wsum: reduce over qc lanes (j-subsets); identical in both n-groups, write from ng==0
#pragma unroll
    for (int k = 0; k < 4; k++) {
        wsum[k] += __shfl_xor_sync(0xffffffffu, wsum[k], 1);
        wsum[k] += __shfl_xor_sync(0xffffffffu, wsum[k], 2);
    }
    if (ng == 0 && qc == 0) {
#pragma unroll
        for (int k = 0; k < 4; k++)
            g_wsum[sk][i0 + mg * 32 + qr + 8 * k] = wsum[k];
    }

#pragma unroll
    for (int mt = 0; mt < 2; mt++) {
        float* pr0 = &g_part[sk][(size_t)(i0 + mg * 32 + mt * 16 + qr) * FOUT];
        float* pr1 = &g_part[sk][(size_t)(i0 + mg * 32 + mt * 16 + qr + 8) * FOUT];
#pragma unroll
        for (int nt = 0; nt < 4; nt++) {
            const int c0 = ng * 32 + nt * 8 + 2 * qc;
            *(float2*)(pr0 + c0) = make_float2(acc[mt][nt][0], acc[mt][nt][1]);
            *(float2*)(pr1 + c0) = make_float2(acc[mt][nt][2], acc[mt][nt][3]);
        }
    }
}

// ===================== K3: combine split-K parts + divide =====================
__global__ __launch_bounds__(512) void k_div(float* __restrict__ out) {
    const int idx = blockIdx.x * 512 + threadIdx.x;
    const int i = idx >> 6;
    const float num = (g_part[0][idx] + g_part[1][idx]) + (g_part[2][idx] + g_part[3][idx]);
    const float den = (g_wsum[0][i] + g_wsum[1][i]) + (g_wsum[2][i] + g_wsum[3][i]);
    out[idx] = num / den;
}

extern "C" void kernel_launch(void* const* d_in, const int* in_sizes, int n_in,
                              void* d_out, int out_size) {
    const float* X  = (const float*)d_in[0];
    const int*   A  = (const int*)d_in[1];
    const float* W  = (const float*)d_in[2];
    const float* a1 = (const float*)d_in[3];
    const float* a2 = (const float*)d_in[4];
    float* out = (float*)d_out;

    cudaFuncSetAttribute(k_gat,  cudaFuncAttributeMaxDynamicSharedMemorySize, GAT_SMEM);
    cudaFuncSetAttribute(k_proj, cudaFuncAttributeMaxDynamicSharedMemorySize, PROJ_SMEM);

    k_proj<<<NN / 32, 256, PROJ_SMEM>>>(X, W, a1, a2);
    k_gat<<<(NN / TI) * SPLIT, 256, GAT_SMEM>>>(A);
    k_div<<<NN * FOUT / 512, 512>>>(out);
}